// round 11
// baseline (speedup 1.0000x reference)
#include <cuda_runtime.h>
#include <cuda_fp16.h>
#include <cuda_bf16.h>
#include <cstdint>

// Problem constants
#define C_DIM   192
#define HEADS   8
#define HD      24          // head dim = 192/8
#define HH      64
#define WW      64
#define NPIX    4096        // 64*64
#define QKV_CH  576         // 3*C

// ---------------- scratch (static device globals; no allocs) ----------------
__device__ float g_xln[C_DIM * NPIX];                 // 3 MB
__device__ float g_qkv[QKV_CH * NPIX];                // 9 MB
__device__ float g_q32[C_DIM * NPIX];                 // 3 MB (dwconv Q out, fp32)
__device__ float g_att[C_DIM * NPIX];                 // 3 MB
// prepacked K (hi/lo fp16, [head][key][32] with cols 24..31 unused) and V fp16
__device__ unsigned short g_kh16[HEADS * NPIX * 32];  // 2 MB
__device__ unsigned short g_kl16[HEADS * NPIX * 32];  // 2 MB
__device__ unsigned short g_vh16[C_DIM * NPIX];       // 1.5 MB

// ---------------- small helpers ----------------
__device__ __forceinline__ float ex2f_fast(float x) {
    float r;
    asm("ex2.approx.f32 %0, %1;" : "=f"(r) : "f"(x));
    return r;
}

// packed fp16x2 exp2
__device__ __forceinline__ uint32_t h2ex2(uint32_t x) {
    uint32_t r;
    asm("ex2.approx.f16x2 %0, %1;" : "=r"(r) : "r"(x));
    return r;
}

// ---------------- Kernel 1: per-pixel LayerNorm over channels ----------------
__global__ void ln_kernel(const float* __restrict__ x,
                          const float* __restrict__ gamma,
                          const float* __restrict__ beta,
                          float* __restrict__ xln) {
    int p = blockIdx.x * blockDim.x + threadIdx.x;
    if (p >= NPIX) return;
    float s = 0.f, s2 = 0.f;
    #pragma unroll 8
    for (int c = 0; c < C_DIM; c++) {
        float v = x[c * NPIX + p];
        s += v;
        s2 = fmaf(v, v, s2);
    }
    const float invC = 1.0f / (float)C_DIM;
    float mean = s * invC;
    float var = s2 * invC - mean * mean;
    float inv = rsqrtf(var + 1e-5f);
    #pragma unroll 8
    for (int c = 0; c < C_DIM; c++) {
        float v = (x[c * NPIX + p] - mean) * inv;
        xln[c * NPIX + p] = fmaf(v, gamma[c], beta[c]);
    }
}

// ---------------- Kernel 2: GEMM  Y[O,N] = W[O,C] @ X[C,N] (+ optional residual) ----
__global__ __launch_bounds__(256) void gemm_kernel(
        const float* __restrict__ W, const float* __restrict__ X,
        const float* __restrict__ resid, float* __restrict__ Y,
        int O, int C, int N) {
    __shared__ __align__(16) float As[16][68];   // [k][o], padded
    __shared__ __align__(16) float Bs[16][64];   // [k][n]
    int tid = threadIdx.x;
    int tx = tid & 15;       // N dir
    int ty = tid >> 4;       // O dir
    int o0 = blockIdx.y * 64;
    int n0 = blockIdx.x * 64;

    float acc[4][4];
    #pragma unroll
    for (int i = 0; i < 4; i++)
        #pragma unroll
        for (int j = 0; j < 4; j++) acc[i][j] = 0.f;

    for (int k0 = 0; k0 < C; k0 += 16) {
        {
            int row = tid >> 2;
            int col = (tid & 3) * 4;
            float4 a = *(const float4*)&W[(o0 + row) * C + k0 + col];
            As[col + 0][row] = a.x;
            As[col + 1][row] = a.y;
            As[col + 2][row] = a.z;
            As[col + 3][row] = a.w;
        }
        {
            int row = tid >> 4;
            int col = (tid & 15) * 4;
            *(float4*)&Bs[row][col] = *(const float4*)&X[(k0 + row) * N + n0 + col];
        }
        __syncthreads();
        #pragma unroll
        for (int k = 0; k < 16; k++) {
            float4 a4 = *(const float4*)&As[k][ty * 4];
            float4 b4 = *(const float4*)&Bs[k][tx * 4];
            float a[4] = {a4.x, a4.y, a4.z, a4.w};
            float b[4] = {b4.x, b4.y, b4.z, b4.w};
            #pragma unroll
            for (int i = 0; i < 4; i++)
                #pragma unroll
                for (int j = 0; j < 4; j++)
                    acc[i][j] = fmaf(a[i], b[j], acc[i][j]);
        }
        __syncthreads();
    }

    #pragma unroll
    for (int i = 0; i < 4; i++) {
        int o = o0 + ty * 4 + i;
        int n = n0 + tx * 4;
        float4 r = make_float4(acc[i][0], acc[i][1], acc[i][2], acc[i][3]);
        if (resid) {
            float4 rv = *(const float4*)&resid[o * N + n];
            r.x += rv.x; r.y += rv.y; r.z += rv.z; r.w += rv.w;
        }
        *(float4*)&Y[o * N + n] = r;
    }
}

// ---------------- Kernel 3: depthwise 3x3 conv + bias, fused K/V prepack ----
__global__ void dwconv_kernel(const float* __restrict__ in,
                              const float* __restrict__ w,
                              const float* __restrict__ b,
                              float* __restrict__ qout,
                              unsigned short* __restrict__ kh,
                              unsigned short* __restrict__ kl,
                              unsigned short* __restrict__ vh) {
    int idx = blockIdx.x * blockDim.x + threadIdx.x;
    if (idx >= QKV_CH * NPIX) return;
    int p = idx & (NPIX - 1);
    int xx = idx & (WW - 1);
    int yy = (idx >> 6) & (HH - 1);
    int ch = idx >> 12;
    const float* wp = &w[ch * 9];
    const float* base = &in[ch * NPIX];
    float acc = b[ch];
    #pragma unroll
    for (int dy = -1; dy <= 1; dy++) {
        int y2 = yy + dy;
        if (y2 < 0 || y2 >= HH) continue;
        #pragma unroll
        for (int dx = -1; dx <= 1; dx++) {
            int x2 = xx + dx;
            if (x2 < 0 || x2 >= WW) continue;
            acc = fmaf(base[y2 * WW + x2], wp[(dy + 1) * 3 + (dx + 1)], acc);
        }
    }
    if (ch < C_DIM) {
        qout[idx] = acc;
    } else if (ch < 2 * C_DIM) {
        int cc = ch - C_DIM;
        int hh2 = cc / HD;
        int dd = cc % HD;
        __half hi = __float2half_rn(acc);
        float lo = acc - __half2float(hi);
        size_t o = ((size_t)(hh2 * NPIX + p)) * 32 + dd;
        kh[o] = __half_as_ushort(hi);
        kl[o] = __half_as_ushort(__float2half_rn(lo));
    } else {
        vh[(size_t)(ch - 2 * C_DIM) * NPIX + p] =
            __half_as_ushort(__float2half_rn(acc));
    }
}

// ---------------- Kernel 4: tensor-core flash attention ----------------
// 256 threads = 8 warps, 128 queries (16/warp), 4096 keys in 128-key smem
// chunks processed as two 64-key half-chunks. Exact k=24 QK^T: m16n8k16
// (d0-15) + m16n8k8 (d16-23), compensated hi/lo fp16. P via ex2.approx.f16x2.
// Row sums from the tensor core via an all-ones V row (row 24).
#define ATT_Q  128
#define ATT_K  128
#define NCHUNK (NPIX / ATT_K)         // 32

// smem layout in halves (dynamic). Q/K rows exactly 24 (48B stride, odd*16B:
// LDSM conflict-free). V rows 136 (272B stride, odd*16B).
#define OQ   0                        // Q hi [128][24]
#define OQL  3072                     // Q lo [128][24]
#define OKB  6144                     // K bufs: 3 x (hi 128*24 + lo 128*24)
#define KBUF 6144
#define OVB  (OKB + 3 * KBUF)         // 24576: V bufs 3 x [32][136]
#define VBUF 4352
#define SM_HALVES (OVB + 3 * VBUF)    // 37632
#define SMEM_BYTES (SM_HALVES * 2)    // 75264

__device__ __forceinline__ void mma16816(float c[4], const uint32_t a[4],
                                         uint32_t b0, uint32_t b1) {
    asm volatile(
        "mma.sync.aligned.m16n8k16.row.col.f32.f16.f16.f32 "
        "{%0,%1,%2,%3}, {%4,%5,%6,%7}, {%8,%9}, {%0,%1,%2,%3};"
        : "+f"(c[0]), "+f"(c[1]), "+f"(c[2]), "+f"(c[3])
        : "r"(a[0]), "r"(a[1]), "r"(a[2]), "r"(a[3]), "r"(b0), "r"(b1));
}

__device__ __forceinline__ void mma1688(float c[4], const uint32_t a[2],
                                        uint32_t b0) {
    asm volatile(
        "mma.sync.aligned.m16n8k8.row.col.f32.f16.f16.f32 "
        "{%0,%1,%2,%3}, {%4,%5}, {%6}, {%0,%1,%2,%3};"
        : "+f"(c[0]), "+f"(c[1]), "+f"(c[2]), "+f"(c[3])
        : "r"(a[0]), "r"(a[1]), "r"(b0));
}

__device__ __forceinline__ void ldsm_x4(uint32_t& r0, uint32_t& r1,
                                        uint32_t& r2, uint32_t& r3, uint32_t addr) {
    asm volatile("ldmatrix.sync.aligned.m8n8.x4.shared.b16 {%0,%1,%2,%3}, [%4];"
                 : "=r"(r0), "=r"(r1), "=r"(r2), "=r"(r3) : "r"(addr));
}

__device__ __forceinline__ void ldsm_x2(uint32_t& r0, uint32_t& r1, uint32_t addr) {
    asm volatile("ldmatrix.sync.aligned.m8n8.x2.shared.b16 {%0,%1}, [%2];"
                 : "=r"(r0), "=r"(r1) : "r"(addr));
}

__device__ __forceinline__ void cp16(uint32_t dst, const void* src) {
    asm volatile("cp.async.cg.shared.global [%0], [%1], 16;"
                 :: "r"(dst), "l"(src));
}

__device__ __forceinline__ uint32_t packh2(float x, float y) {
    __half2 h = __floats2half2_rn(x, y);   // low <- x, high <- y
    return *(uint32_t*)&h;
}

__global__ __launch_bounds__(256, 2) void attn_mma_kernel(
        const float* __restrict__ q32,
        const unsigned short* __restrict__ kh,
        const unsigned short* __restrict__ kl,
        const unsigned short* __restrict__ vh,
        const float* __restrict__ temp,
        float* __restrict__ att) {
    extern __shared__ __align__(16) __half sm[];
    const int tid = threadIdx.x;
    const int lane = tid & 31;
    const int warp = tid >> 5;
    const int g = lane >> 2;      // row group 0..7
    const int t = lane & 3;       // thread-in-group

    const int h = blockIdx.y;
    const int q0 = blockIdx.x * ATT_Q;
    const float scale = temp[h] * 1.4426950408889634f;  // temperature * log2(e)

    const float* qg = q32 + (h * HD) * NPIX;
    const unsigned short* khg = kh + (size_t)h * NPIX * 32;
    const unsigned short* klg = kl + (size_t)h * NPIX * 32;
    const unsigned short* vg  = vh + (size_t)(h * HD) * NPIX;

    const uint32_t smb = (uint32_t)__cvta_generic_to_shared(sm);

    // ---- init: V rows 24..31 of each buffer (row 24 = ones, rest zero) ----
    for (int i = tid; i < 3 * 8 * 136; i += 256) {
        int buf = i / 1088;
        int rem = i - buf * 1088;
        int row = rem / 136;
        int col = rem - row * 136;
        sm[OVB + buf * VBUF + (24 + row) * 136 + col] =
            (row == 0) ? __float2half_rn(1.0f) : __ushort_as_half(0);
    }

    // ---- cp.async issue for one 128-key chunk ----
    auto issue_chunk = [&](int b, int m0) {
        uint32_t kdstH = smb + (OKB + b * KBUF) * 2;
        uint32_t kdstL = kdstH + 3072 * 2;
        uint32_t vdst  = smb + (OVB + b * VBUF) * 2;
        #pragma unroll
        for (int i = tid; i < 1152; i += 256) {
            if (i < 768) {
                int r = i;
                int part = r >= 384;
                r -= part * 384;
                int key = r / 3;
                int c = r - key * 3;
                const unsigned short* src =
                    (part ? klg : khg) + (size_t)(m0 + key) * 32 + c * 8;
                uint32_t dst = (part ? kdstL : kdstH) + (key * 24 + c * 8) * 2;
                cp16(dst, src);
            } else {
                int r = i - 768;
                int d = r >> 4;
                int c2 = r & 15;
                const unsigned short* src = vg + (size_t)d * NPIX + m0 + c2 * 8;
                uint32_t dst = vdst + (d * 136 + c2 * 8) * 2;
                cp16(dst, src);
            }
        }
        asm volatile("cp.async.commit_group;" ::: "memory");
    };
    issue_chunk(0, 0);
    issue_chunk(1, ATT_K);

    // ---- stage Q (scaled, hi/lo split), rows exactly 24 halves ----
    #pragma unroll
    for (int i = 0; i < 6; i++) {
        int e = tid + i * 256;            // 128 q * 12 d-pairs = 1536
        int dp = e >> 7;
        int qq = e & 127;
        float v0 = qg[(2 * dp) * NPIX + q0 + qq] * scale;
        float v1 = qg[(2 * dp + 1) * NPIX + q0 + qq] * scale;
        __half h0 = __float2half_rn(v0);
        __half h1 = __float2half_rn(v1);
        __half l0 = __float2half_rn(v0 - __half2float(h0));
        __half l1 = __float2half_rn(v1 - __half2float(h1));
        *(__half2*)&sm[OQ  + qq * 24 + 2 * dp] = __halves2half2(h0, h1);
        *(__half2*)&sm[OQL + qq * 24 + 2 * dp] = __halves2half2(l0, l1);
    }
    __syncthreads();

    // ---- Q A-fragments: k16 (d0-15, 4 regs) + k8 (d16-23, 2 regs) ----
    uint32_t aqh16[4], aql16[4], aqh8[2], aql8[2];
    const int qr = warp * 16 + g;
    {
        int db = t * 2;
        aqh16[0] = *(const uint32_t*)&sm[OQ + qr * 24 + db];
        aqh16[1] = *(const uint32_t*)&sm[OQ + (qr + 8) * 24 + db];
        aqh16[2] = *(const uint32_t*)&sm[OQ + qr * 24 + db + 8];
        aqh16[3] = *(const uint32_t*)&sm[OQ + (qr + 8) * 24 + db + 8];
        aqh8[0]  = *(const uint32_t*)&sm[OQ + qr * 24 + 16 + db];
        aqh8[1]  = *(const uint32_t*)&sm[OQ + (qr + 8) * 24 + 16 + db];
        aql16[0] = *(const uint32_t*)&sm[OQL + qr * 24 + db];
        aql16[1] = *(const uint32_t*)&sm[OQL + (qr + 8) * 24 + db];
        aql16[2] = *(const uint32_t*)&sm[OQL + qr * 24 + db + 8];
        aql16[3] = *(const uint32_t*)&sm[OQL + (qr + 8) * 24 + db + 8];
        aql8[0]  = *(const uint32_t*)&sm[OQL + qr * 24 + 16 + db];
        aql8[1]  = *(const uint32_t*)&sm[OQL + (qr + 8) * 24 + 16 + db];
    }

    // per-lane ldmatrix offsets (bytes, relative to K buffer base)
    const int l7 = lane & 7;
    const int grp = lane >> 3;
    // x4: tiles (hi d0-7, hi d8-15, hi d16-23, lo d0-7)
    const uint32_t koff4 = ((grp < 3 ? grp * 8 : 3072) + l7 * 24) * 2;
    // x2: tiles (lo d8-15, lo d16-23) — lanes 0..15 supply addresses
    const uint32_t koff2 = (3072 + 8 + (grp & 1) * 8 + l7 * 24) * 2;
    const uint32_t loff_v = (l7 * 136 + (grp * 8)) * 2;

    // out[0..2] = PV tiles (d 0..23); out[3] = ones-row tile (row sums)
    float out[4][4];
    #pragma unroll
    for (int i = 0; i < 4; i++)
        #pragma unroll
        for (int j = 0; j < 4; j++) out[i][j] = 0.f;
    float m_a = -1e30f, m_b = -1e30f;   // row maxes (log2 units)

    for (int ch = 0; ch < NCHUNK; ch++) {
        if (ch < NCHUNK - 1)
            asm volatile("cp.async.wait_group 1;" ::: "memory");
        else
            asm volatile("cp.async.wait_group 0;" ::: "memory");
        __syncthreads();
        if (ch + 2 < NCHUNK) issue_chunk((ch + 2) % 3, (ch + 2) * ATT_K);

        const int b = ch % 3;
        const uint32_t kbase = smb + (OKB + b * KBUF) * 2;
        const uint32_t vbase = smb + (OVB + b * VBUF) * 2;

        #pragma unroll
        for (int hc = 0; hc < 2; hc++) {
            const uint32_t krow0 = (uint32_t)(hc * 64) * 48;   // 24 halves*2B
            const uint32_t vcol0 = (uint32_t)(hc * 64) * 2;

            // ---- S = Q K^T exact k=24 (k16 + k8), compensated ----
            float s[8][4];
            #pragma unroll
            for (int nt = 0; nt < 8; nt++) {
                uint32_t base = kbase + krow0 + (uint32_t)(nt * 8) * 48;
                uint32_t h0, h1, h2, L0, L1, L2;
                ldsm_x4(h0, h1, h2, L0, base + koff4);
                ldsm_x2(L1, L2, base + koff2);
                s[nt][0] = s[nt][1] = s[nt][2] = s[nt][3] = 0.f;
                mma16816(s[nt], aqh16, h0, h1);
                mma1688(s[nt], aqh8, h2);
                mma16816(s[nt], aql16, h0, h1);
                mma1688(s[nt], aql8, h2);
                mma16816(s[nt], aqh16, L0, L1);
                mma1688(s[nt], aqh8, L2);
            }

            // ---- online softmax (log2 domain) ----
            float ra = -1e30f, rb = -1e30f;
            #pragma unroll
            for (int nt = 0; nt < 8; nt++) {
                ra = fmaxf(ra, fmaxf(s[nt][0], s[nt][1]));
                rb = fmaxf(rb, fmaxf(s[nt][2], s[nt][3]));
            }
            ra = fmaxf(ra, __shfl_xor_sync(0xffffffffu, ra, 1));
            ra = fmaxf(ra, __shfl_xor_sync(0xffffffffu, ra, 2));
            rb = fmaxf(rb, __shfl_xor_sync(0xffffffffu, rb, 1));
            rb = fmaxf(rb, __shfl_xor_sync(0xffffffffu, rb, 2));
            float nma = fmaxf(m_a, ra);
            float nmb = fmaxf(m_b, rb);
            float ala = ex2f_fast(m_a - nma);
            float alb = ex2f_fast(m_b - nmb);
            m_a = nma; m_b = nmb;
            #pragma unroll
            for (int dnt = 0; dnt < 4; dnt++) {
                out[dnt][0] *= ala; out[dnt][1] *= ala;
                out[dnt][2] *= alb; out[dnt][3] *= alb;
            }

            // ---- P = exp2(S - m) in packed fp16 (A-layout fragments) ----
            uint32_t pa[4][4];
            #pragma unroll
            for (int kv = 0; kv < 4; kv++) {
                pa[kv][0] = h2ex2(packh2(s[2 * kv][0] - m_a,     s[2 * kv][1] - m_a));
                pa[kv][1] = h2ex2(packh2(s[2 * kv][2] - m_b,     s[2 * kv][3] - m_b));
                pa[kv][2] = h2ex2(packh2(s[2 * kv + 1][0] - m_a, s[2 * kv + 1][1] - m_a));
                pa[kv][3] = h2ex2(packh2(s[2 * kv + 1][2] - m_b, s[2 * kv + 1][3] - m_b));
            }

            // ---- out += P V  (4th tile = ones row -> row sums) ----
            #pragma unroll
            for (int dnt = 0; dnt < 4; dnt++) {
                uint32_t base = vbase + vcol0 + (uint32_t)(dnt * 8) * 272 + loff_v;
                uint32_t v0, v1, v2, v3, v4, v5, v6, v7;
                ldsm_x4(v0, v1, v2, v3, base);        // keys 0..31
                ldsm_x4(v4, v5, v6, v7, base + 64);   // keys 32..63
                mma16816(out[dnt], pa[0], v0, v1);
                mma16816(out[dnt], pa[1], v2, v3);
                mma16816(out[dnt], pa[2], v4, v5);
                mma16816(out[dnt], pa[3], v6, v7);
            }
        }
    }

    // ---- epilogue: l lives in out[3][0]/[2] of the t=0 lane of each quad ----
    float l_a = __shfl_sync(0xffffffffu, out[3][0], lane & ~3);
    float l_b = __shfl_sync(0xffffffffu, out[3][2], lane & ~3);
    float inva = 1.0f / l_a;
    float invb = 1.0f / l_b;
    int qa = q0 + warp * 16 + g;
    int qb = qa + 8;
    #pragma unroll
    for (int dnt = 0; dnt < 3; dnt++) {
        int c0 = h * HD + dnt * 8 + t * 2;
        att[c0 * NPIX + qa]       = out[dnt][0] * inva;
        att[(c0 + 1) * NPIX + qa] = out[dnt][1] * inva;
        att[c0 * NPIX + qb]       = out[dnt][2] * invb;
        att[(c0 + 1) * NPIX + qb] = out[dnt][3] * invb;
    }
}

// ---------------- launch ----------------
extern "C" void kernel_launch(void* const* d_in, const int* in_sizes, int n_in,
                              void* d_out, int out_size) {
    const float* x      = (const float*)d_in[0];   // [192,4096]
    const float* gamma  = (const float*)d_in[1];   // [192]
    const float* beta   = (const float*)d_in[2];   // [192]
    const float* w_qkv  = (const float*)d_in[3];   // [576,192]
    const float* w_dw   = (const float*)d_in[4];   // [576,9]
    const float* b_dw   = (const float*)d_in[5];   // [576]
    const float* w_proj = (const float*)d_in[6];   // [192,192]
    const float* temper = (const float*)d_in[7];   // [8]
    float* out = (float*)d_out;

    float *xln, *qkvb, *q32, *att;
    unsigned short *kh, *kl, *vh;
    cudaGetSymbolAddress((void**)&xln,  g_xln);
    cudaGetSymbolAddress((void**)&qkvb, g_qkv);
    cudaGetSymbolAddress((void**)&q32,  g_q32);
    cudaGetSymbolAddress((void**)&att,  g_att);
    cudaGetSymbolAddress((void**)&kh,   g_kh16);
    cudaGetSymbolAddress((void**)&kl,   g_kl16);
    cudaGetSymbolAddress((void**)&vh,   g_vh16);

    cudaFuncSetAttribute(attn_mma_kernel,
                         cudaFuncAttributeMaxDynamicSharedMemorySize, SMEM_BYTES);

    // 1. LayerNorm
    ln_kernel<<<NPIX / 256, 256>>>(x, gamma, beta, xln);

    // 2. qkv = w_qkv @ xln   [576,4096]
    {
        dim3 grid(NPIX / 64, QKV_CH / 64);
        gemm_kernel<<<grid, 256>>>(w_qkv, xln, nullptr, qkvb, QKV_CH, C_DIM, NPIX);
    }

    // 3. depthwise 3x3 + bias, fused K/V fp16 prepack
    dwconv_kernel<<<(QKV_CH * NPIX) / 256, 256>>>(qkvb, w_dw, b_dw,
                                                  q32, kh, kl, vh);

    // 4. tensor-core flash attention -> att [192,4096]
    {
        dim3 grid(NPIX / ATT_Q, HEADS);
        attn_mma_kernel<<<grid, 256, SMEM_BYTES>>>(q32, kh, kl, vh, temper, att);
    }

    // 5. out = w_proj @ att + x
    {
        dim3 grid(NPIX / 64, C_DIM / 64);
        gemm_kernel<<<grid, 256>>>(w_proj, att, x, out, C_DIM, C_DIM, NPIX);
    }
}

// round 12
// speedup vs baseline: 1.4949x; 1.4949x over previous
#include <cuda_runtime.h>
#include <cuda_fp16.h>
#include <cuda_bf16.h>
#include <cstdint>

// Problem constants
#define C_DIM   192
#define HEADS   8
#define HD      24          // head dim = 192/8
#define HH      64
#define WW      64
#define NPIX    4096        // 64*64
#define QKV_CH  576         // 3*C

// ---------------- scratch (static device globals; no allocs) ----------------
__device__ float g_xln[C_DIM * NPIX];                 // 3 MB
__device__ float g_qkv[QKV_CH * NPIX];                // 9 MB
__device__ float g_q32[C_DIM * NPIX];                 // 3 MB (dwconv Q out, fp32)
__device__ float g_att[C_DIM * NPIX];                 // 3 MB
// prepacked K (hi/lo fp16, [head][key][32] with cols 24..31 zero) and V fp16
__device__ unsigned short g_kh16[HEADS * NPIX * 32];  // 2 MB
__device__ unsigned short g_kl16[HEADS * NPIX * 32];  // 2 MB
__device__ unsigned short g_vh16[C_DIM * NPIX];       // 1.5 MB

// ---------------- small helpers ----------------
__device__ __forceinline__ float ex2f_fast(float x) {
    float r;
    asm("ex2.approx.f32 %0, %1;" : "=f"(r) : "f"(x));
    return r;
}

// packed fp16x2 exp2
__device__ __forceinline__ uint32_t h2ex2(uint32_t x) {
    uint32_t r;
    asm("ex2.approx.f16x2 %0, %1;" : "=r"(r) : "r"(x));
    return r;
}

// ---------------- Kernel 1: per-pixel LayerNorm over channels ----------------
__global__ void ln_kernel(const float* __restrict__ x,
                          const float* __restrict__ gamma,
                          const float* __restrict__ beta,
                          float* __restrict__ xln) {
    int p = blockIdx.x * blockDim.x + threadIdx.x;
    if (p >= NPIX) return;
    float s = 0.f, s2 = 0.f;
    #pragma unroll 8
    for (int c = 0; c < C_DIM; c++) {
        float v = x[c * NPIX + p];
        s += v;
        s2 = fmaf(v, v, s2);
    }
    const float invC = 1.0f / (float)C_DIM;
    float mean = s * invC;
    float var = s2 * invC - mean * mean;
    float inv = rsqrtf(var + 1e-5f);
    #pragma unroll 8
    for (int c = 0; c < C_DIM; c++) {
        float v = (x[c * NPIX + p] - mean) * inv;
        xln[c * NPIX + p] = fmaf(v, gamma[c], beta[c]);
    }
}

// ---------------- Kernel 2: GEMM  Y[O,N] = W[O,C] @ X[C,N] (+ optional residual) ----
__global__ __launch_bounds__(256) void gemm_kernel(
        const float* __restrict__ W, const float* __restrict__ X,
        const float* __restrict__ resid, float* __restrict__ Y,
        int O, int C, int N) {
    __shared__ __align__(16) float As[16][68];   // [k][o], padded
    __shared__ __align__(16) float Bs[16][64];   // [k][n]
    int tid = threadIdx.x;
    int tx = tid & 15;       // N dir
    int ty = tid >> 4;       // O dir
    int o0 = blockIdx.y * 64;
    int n0 = blockIdx.x * 64;

    float acc[4][4];
    #pragma unroll
    for (int i = 0; i < 4; i++)
        #pragma unroll
        for (int j = 0; j < 4; j++) acc[i][j] = 0.f;

    for (int k0 = 0; k0 < C; k0 += 16) {
        {
            int row = tid >> 2;
            int col = (tid & 3) * 4;
            float4 a = *(const float4*)&W[(o0 + row) * C + k0 + col];
            As[col + 0][row] = a.x;
            As[col + 1][row] = a.y;
            As[col + 2][row] = a.z;
            As[col + 3][row] = a.w;
        }
        {
            int row = tid >> 4;
            int col = (tid & 15) * 4;
            *(float4*)&Bs[row][col] = *(const float4*)&X[(k0 + row) * N + n0 + col];
        }
        __syncthreads();
        #pragma unroll
        for (int k = 0; k < 16; k++) {
            float4 a4 = *(const float4*)&As[k][ty * 4];
            float4 b4 = *(const float4*)&Bs[k][tx * 4];
            float a[4] = {a4.x, a4.y, a4.z, a4.w};
            float b[4] = {b4.x, b4.y, b4.z, b4.w};
            #pragma unroll
            for (int i = 0; i < 4; i++)
                #pragma unroll
                for (int j = 0; j < 4; j++)
                    acc[i][j] = fmaf(a[i], b[j], acc[i][j]);
        }
        __syncthreads();
    }

    #pragma unroll
    for (int i = 0; i < 4; i++) {
        int o = o0 + ty * 4 + i;
        int n = n0 + tx * 4;
        float4 r = make_float4(acc[i][0], acc[i][1], acc[i][2], acc[i][3]);
        if (resid) {
            float4 rv = *(const float4*)&resid[o * N + n];
            r.x += rv.x; r.y += rv.y; r.z += rv.z; r.w += rv.w;
        }
        *(float4*)&Y[o * N + n] = r;
    }
}

// ---------------- Kernel 3: depthwise 3x3 conv + bias, fused K/V prepack ----
__global__ void dwconv_kernel(const float* __restrict__ in,
                              const float* __restrict__ w,
                              const float* __restrict__ b,
                              float* __restrict__ qout,
                              unsigned short* __restrict__ kh,
                              unsigned short* __restrict__ kl,
                              unsigned short* __restrict__ vh) {
    int idx = blockIdx.x * blockDim.x + threadIdx.x;
    if (idx >= QKV_CH * NPIX) return;
    int p = idx & (NPIX - 1);
    int xx = idx & (WW - 1);
    int yy = (idx >> 6) & (HH - 1);
    int ch = idx >> 12;
    const float* wp = &w[ch * 9];
    const float* base = &in[ch * NPIX];
    float acc = b[ch];
    #pragma unroll
    for (int dy = -1; dy <= 1; dy++) {
        int y2 = yy + dy;
        if (y2 < 0 || y2 >= HH) continue;
        #pragma unroll
        for (int dx = -1; dx <= 1; dx++) {
            int x2 = xx + dx;
            if (x2 < 0 || x2 >= WW) continue;
            acc = fmaf(base[y2 * WW + x2], wp[(dy + 1) * 3 + (dx + 1)], acc);
        }
    }
    if (ch < C_DIM) {
        qout[idx] = acc;
    } else if (ch < 2 * C_DIM) {
        int cc = ch - C_DIM;
        int hh2 = cc / HD;
        int dd = cc % HD;
        __half hi = __float2half_rn(acc);
        float lo = acc - __half2float(hi);
        size_t o = ((size_t)(hh2 * NPIX + p)) * 32 + dd;
        kh[o] = __half_as_ushort(hi);
        kl[o] = __half_as_ushort(__float2half_rn(lo));
    } else {
        vh[(size_t)(ch - 2 * C_DIM) * NPIX + p] =
            __half_as_ushort(__float2half_rn(acc));
    }
}

// ---------------- Kernel 4: tensor-core flash attention ----------------
// 256 threads = 8 warps, 128 queries (16/warp), 4096 keys in 128-key smem
// chunks (two 64-key compute halves). Round-10 math: k=32 zero-padded QK^T
// with compensated hi/lo fp16 (6x m16n8k16 per n-tile), P via ex2.approx.f16x2,
// row sums via an all-ones V row. Q fragments built directly from global
// (no Q smem). 3-stage cp.async pipeline, 1 barrier per 128 keys.
#define ATT_Q  128
#define ATT_K  128
#define NCHUNK (NPIX / ATT_K)         // 32

// smem layout in halves (dynamic).
// K bufs: 3 x { hi [128][40], lo [128][40] }  (cols 24..31 zeroed once)
// V bufs: 3 x [32][136]  (rows 0..23 data, row 24 ones, 25..31 zeros)
#define OKB  0
#define KBUF 10240                    // per buf (hi 5120 + lo 5120)
#define OVB  (3 * KBUF)               // 30720
#define VBUF 4352                     // 32*136
#define SM_HALVES (OVB + 3 * VBUF)    // 43776
#define SMEM_BYTES (SM_HALVES * 2)    // 87552

__device__ __forceinline__ void mma16816(float c[4], const uint32_t a[4],
                                         uint32_t b0, uint32_t b1) {
    asm volatile(
        "mma.sync.aligned.m16n8k16.row.col.f32.f16.f16.f32 "
        "{%0,%1,%2,%3}, {%4,%5,%6,%7}, {%8,%9}, {%0,%1,%2,%3};"
        : "+f"(c[0]), "+f"(c[1]), "+f"(c[2]), "+f"(c[3])
        : "r"(a[0]), "r"(a[1]), "r"(a[2]), "r"(a[3]), "r"(b0), "r"(b1));
}

__device__ __forceinline__ void ldsm_x4(uint32_t& r0, uint32_t& r1,
                                        uint32_t& r2, uint32_t& r3, uint32_t addr) {
    asm volatile("ldmatrix.sync.aligned.m8n8.x4.shared.b16 {%0,%1,%2,%3}, [%4];"
                 : "=r"(r0), "=r"(r1), "=r"(r2), "=r"(r3) : "r"(addr));
}

__device__ __forceinline__ void cp16(uint32_t dst, const void* src) {
    asm volatile("cp.async.cg.shared.global [%0], [%1], 16;"
                 :: "r"(dst), "l"(src));
}

__device__ __forceinline__ uint32_t packh2(float x, float y) {
    __half2 h = __floats2half2_rn(x, y);   // low <- x, high <- y
    return *(uint32_t*)&h;
}

__global__ __launch_bounds__(256, 2) void attn_mma_kernel(
        const float* __restrict__ q32,
        const unsigned short* __restrict__ kh,
        const unsigned short* __restrict__ kl,
        const unsigned short* __restrict__ vh,
        const float* __restrict__ temp,
        float* __restrict__ att) {
    extern __shared__ __align__(16) __half sm[];
    const int tid = threadIdx.x;
    const int lane = tid & 31;
    const int warp = tid >> 5;
    const int g = lane >> 2;      // row group 0..7
    const int t = lane & 3;       // thread-in-group

    const int h = blockIdx.y;
    const int q0 = blockIdx.x * ATT_Q;
    const float scale = temp[h] * 1.4426950408889634f;  // temperature * log2(e)

    const float* qg = q32 + (h * HD) * NPIX;
    const unsigned short* khg = kh + (size_t)h * NPIX * 32;
    const unsigned short* klg = kl + (size_t)h * NPIX * 32;
    const unsigned short* vg  = vh + (size_t)(h * HD) * NPIX;

    const uint32_t smb = (uint32_t)__cvta_generic_to_shared(sm);

    // ---- one-time init: K pad cols 24..31 (all bufs), V rows 24..31 ----
    {
        uint32_t* smw = (uint32_t*)sm;
        // K pads: 3 bufs x 2 parts x 128 rows x 4 words
        for (int i = tid; i < 3072; i += 256) {
            int wds = i & 3;
            int r2 = i >> 2;               // row index 0..767
            int buf = r2 >> 8;             // /256
            int rem = r2 & 255;
            int part = rem >> 7;
            int row = rem & 127;
            int halfoff = OKB + buf * KBUF + part * 5120 + row * 40 + 24;
            smw[(halfoff >> 1) + wds] = 0;
        }
        // V rows 24..31 of each buffer: row 24 = 1.0h, rows 25..31 = 0
        for (int i = tid; i < 3 * 8 * 136; i += 256) {
            int buf = i / 1088;
            int rem = i - buf * 1088;
            int row = rem / 136;
            int col = rem - row * 136;
            sm[OVB + buf * VBUF + (24 + row) * 136 + col] =
                (row == 0) ? __float2half_rn(1.0f) : __ushort_as_half(0);
        }
    }

    // ---- cp.async issue for one 128-key chunk ----
    auto issue_chunk = [&](int b, int m0) {
        uint32_t kdstH = smb + (OKB + b * KBUF) * 2;
        uint32_t kdstL = kdstH + 5120 * 2;
        uint32_t vdst  = smb + (OVB + b * VBUF) * 2;
        #pragma unroll
        for (int i = tid; i < 1152; i += 256) {
            if (i < 768) {
                int r = i;
                int part = r >= 384;
                r -= part * 384;
                int key = r / 3;            // 0..127
                int c = r - key * 3;        // 0..2 (8-half groups of 24)
                const unsigned short* src =
                    (part ? klg : khg) + (size_t)(m0 + key) * 32 + c * 8;
                uint32_t dst = (part ? kdstL : kdstH) + (key * 40 + c * 8) * 2;
                cp16(dst, src);
            } else {
                int r = i - 768;            // 0..383
                int d = r >> 4;             // 0..23
                int c2 = r & 15;            // 16 x 8-key groups
                const unsigned short* src = vg + (size_t)d * NPIX + m0 + c2 * 8;
                uint32_t dst = vdst + (d * 136 + c2 * 8) * 2;
                cp16(dst, src);
            }
        }
        asm volatile("cp.async.commit_group;" ::: "memory");
    };
    issue_chunk(0, 0);
    issue_chunk(1, ATT_K);

    // ---- Q A-fragments built directly from global (one-time, scattered) ----
    uint32_t aqh[2][4], aql[2][4];
    const int qr = warp * 16 + g;
    #pragma unroll
    for (int ks = 0; ks < 2; ks++) {
        #pragma unroll
        for (int r = 0; r < 4; r++) {
            int d0 = ks * 16 + t * 2 + ((r >= 2) ? 8 : 0);
            int qq = q0 + qr + (r & 1) * 8;
            if (d0 < HD) {
                float v0 = qg[d0 * NPIX + qq] * scale;
                float v1 = qg[(d0 + 1) * NPIX + qq] * scale;
                __half h0 = __float2half_rn(v0);
                __half h1 = __float2half_rn(v1);
                aqh[ks][r] = ((uint32_t)__half_as_ushort(h1) << 16) |
                             __half_as_ushort(h0);
                __half l0 = __float2half_rn(v0 - __half2float(h0));
                __half l1 = __float2half_rn(v1 - __half2float(h1));
                aql[ks][r] = ((uint32_t)__half_as_ushort(l1) << 16) |
                             __half_as_ushort(l0);
            } else {
                aqh[ks][r] = 0;
                aql[ks][r] = 0;
            }
        }
    }

    // per-lane ldmatrix offsets (bytes)
    const int l7 = lane & 7;
    const int grp = lane >> 3;
    const uint32_t loff_k = (l7 * 40 + grp * 8) * 2;
    const uint32_t loff_v = (l7 * 136 + grp * 8) * 2;

    // out[0..2] = PV tiles (d 0..23); out[3] = ones-row tile (row sums)
    float out[4][4];
    #pragma unroll
    for (int i = 0; i < 4; i++)
        #pragma unroll
        for (int j = 0; j < 4; j++) out[i][j] = 0.f;
    float m_a = -1e30f, m_b = -1e30f;   // row maxes (log2 units)

    for (int ch = 0; ch < NCHUNK; ch++) {
        if (ch < NCHUNK - 1)
            asm volatile("cp.async.wait_group 1;" ::: "memory");
        else
            asm volatile("cp.async.wait_group 0;" ::: "memory");
        __syncthreads();
        if (ch + 2 < NCHUNK) issue_chunk((ch + 2) % 3, (ch + 2) * ATT_K);

        const int b = ch % 3;
        const uint32_t kbase = smb + (OKB + b * KBUF) * 2;
        const uint32_t vbase = smb + (OVB + b * VBUF) * 2;

        #pragma unroll
        for (int hc = 0; hc < 2; hc++) {
            const uint32_t kaddr_h = kbase + (uint32_t)hc * 5120 + loff_k;
            const uint32_t kaddr_l = kaddr_h + 5120 * 2;
            const uint32_t vaddr   = vbase + (uint32_t)hc * 128 + loff_v;

            // ---- S = Q K^T (compensated, k=32 zero-padded) ----
            float s[8][4];
            #pragma unroll
            for (int nt = 0; nt < 8; nt++) {
                uint32_t h0, h1, h2, h3, L0, L1, L2, L3;
                ldsm_x4(h0, h1, h2, h3, kaddr_h + nt * 640);
                ldsm_x4(L0, L1, L2, L3, kaddr_l + nt * 640);
                s[nt][0] = s[nt][1] = s[nt][2] = s[nt][3] = 0.f;
                mma16816(s[nt], aqh[0], h0, h1);
                mma16816(s[nt], aqh[1], h2, h3);
                mma16816(s[nt], aql[0], h0, h1);
                mma16816(s[nt], aql[1], h2, h3);
                mma16816(s[nt], aqh[0], L0, L1);
                mma16816(s[nt], aqh[1], L2, L3);
            }

            // ---- online softmax (log2 domain) ----
            float ra = -1e30f, rb = -1e30f;
            #pragma unroll
            for (int nt = 0; nt < 8; nt++) {
                ra = fmaxf(ra, fmaxf(s[nt][0], s[nt][1]));
                rb = fmaxf(rb, fmaxf(s[nt][2], s[nt][3]));
            }
            ra = fmaxf(ra, __shfl_xor_sync(0xffffffffu, ra, 1));
            ra = fmaxf(ra, __shfl_xor_sync(0xffffffffu, ra, 2));
            rb = fmaxf(rb, __shfl_xor_sync(0xffffffffu, rb, 1));
            rb = fmaxf(rb, __shfl_xor_sync(0xffffffffu, rb, 2));
            float nma = fmaxf(m_a, ra);
            float nmb = fmaxf(m_b, rb);
            float ala = ex2f_fast(m_a - nma);
            float alb = ex2f_fast(m_b - nmb);
            m_a = nma; m_b = nmb;
            #pragma unroll
            for (int dnt = 0; dnt < 4; dnt++) {
                out[dnt][0] *= ala; out[dnt][1] *= ala;
                out[dnt][2] *= alb; out[dnt][3] *= alb;
            }

            // ---- P = exp2(S - m) in packed fp16 (A-layout fragments) ----
            uint32_t pa[4][4];
            #pragma unroll
            for (int kv = 0; kv < 4; kv++) {
                pa[kv][0] = h2ex2(packh2(s[2 * kv][0] - m_a,     s[2 * kv][1] - m_a));
                pa[kv][1] = h2ex2(packh2(s[2 * kv][2] - m_b,     s[2 * kv][3] - m_b));
                pa[kv][2] = h2ex2(packh2(s[2 * kv + 1][0] - m_a, s[2 * kv + 1][1] - m_a));
                pa[kv][3] = h2ex2(packh2(s[2 * kv + 1][2] - m_b, s[2 * kv + 1][3] - m_b));
            }

            // ---- out += P V  (4th tile = ones row -> row sums) ----
            #pragma unroll
            for (int dnt = 0; dnt < 4; dnt++) {
                uint32_t base = vaddr + (uint32_t)(dnt * 8) * 272;
                uint32_t v0, v1, v2, v3, v4, v5, v6, v7;
                ldsm_x4(v0, v1, v2, v3, base);        // keys 0..31
                ldsm_x4(v4, v5, v6, v7, base + 64);   // keys 32..63
                mma16816(out[dnt], pa[0], v0, v1);
                mma16816(out[dnt], pa[1], v2, v3);
                mma16816(out[dnt], pa[2], v4, v5);
                mma16816(out[dnt], pa[3], v6, v7);
            }
        }
    }

    // ---- epilogue: l lives in out[3][0]/[2] of the t=0 lane of each quad ----
    float l_a = __shfl_sync(0xffffffffu, out[3][0], lane & ~3);
    float l_b = __shfl_sync(0xffffffffu, out[3][2], lane & ~3);
    float inva = 1.0f / l_a;
    float invb = 1.0f / l_b;
    int qa = q0 + warp * 16 + g;
    int qb = qa + 8;
    #pragma unroll
    for (int dnt = 0; dnt < 3; dnt++) {
        int c0 = h * HD + dnt * 8 + t * 2;
        att[c0 * NPIX + qa]       = out[dnt][0] * inva;
        att[(c0 + 1) * NPIX + qa] = out[dnt][1] * inva;
        att[c0 * NPIX + qb]       = out[dnt][2] * invb;
        att[(c0 + 1) * NPIX + qb] = out[dnt][3] * invb;
    }
}

// ---------------- launch ----------------
extern "C" void kernel_launch(void* const* d_in, const int* in_sizes, int n_in,
                              void* d_out, int out_size) {
    const float* x      = (const float*)d_in[0];   // [192,4096]
    const float* gamma  = (const float*)d_in[1];   // [192]
    const float* beta   = (const float*)d_in[2];   // [192]
    const float* w_qkv  = (const float*)d_in[3];   // [576,192]
    const float* w_dw   = (const float*)d_in[4];   // [576,9]
    const float* b_dw   = (const float*)d_in[5];   // [576]
    const float* w_proj = (const float*)d_in[6];   // [192,192]
    const float* temper = (const float*)d_in[7];   // [8]
    float* out = (float*)d_out;

    float *xln, *qkvb, *q32, *att;
    unsigned short *kh, *kl, *vh;
    cudaGetSymbolAddress((void**)&xln,  g_xln);
    cudaGetSymbolAddress((void**)&qkvb, g_qkv);
    cudaGetSymbolAddress((void**)&q32,  g_q32);
    cudaGetSymbolAddress((void**)&att,  g_att);
    cudaGetSymbolAddress((void**)&kh,   g_kh16);
    cudaGetSymbolAddress((void**)&kl,   g_kl16);
    cudaGetSymbolAddress((void**)&vh,   g_vh16);

    cudaFuncSetAttribute(attn_mma_kernel,
                         cudaFuncAttributeMaxDynamicSharedMemorySize, SMEM_BYTES);

    // 1. LayerNorm
    ln_kernel<<<NPIX / 256, 256>>>(x, gamma, beta, xln);

    // 2. qkv = w_qkv @ xln   [576,4096]
    {
        dim3 grid(NPIX / 64, QKV_CH / 64);
        gemm_kernel<<<grid, 256>>>(w_qkv, xln, nullptr, qkvb, QKV_CH, C_DIM, NPIX);
    }

    // 3. depthwise 3x3 + bias, fused K/V fp16 prepack
    dwconv_kernel<<<(QKV_CH * NPIX) / 256, 256>>>(qkvb, w_dw, b_dw,
                                                  q32, kh, kl, vh);

    // 4. tensor-core flash attention -> att [192,4096]
    {
        dim3 grid(NPIX / ATT_Q, HEADS);
        attn_mma_kernel<<<grid, 256, SMEM_BYTES>>>(q32, kh, kl, vh, temper, att);
    }

    // 5. out = w_proj @ att + x
    {
        dim3 grid(NPIX / 64, C_DIM / 64);
        gemm_kernel<<<grid, 256>>>(w_proj, att, x, out, C_DIM, C_DIM, NPIX);
    }
}

// round 13
// speedup vs baseline: 1.6561x; 1.1078x over previous
#include <cuda_runtime.h>
#include <cuda_fp16.h>
#include <cuda_bf16.h>
#include <cstdint>

// Problem constants
#define C_DIM   192
#define HEADS   8
#define HD      24          // head dim = 192/8
#define HH      64
#define WW      64
#define NPIX    4096        // 64*64
#define QKV_CH  576         // 3*C

// ---------------- scratch (static device globals; no allocs) ----------------
__device__ float g_qkv[QKV_CH * NPIX];                // 9 MB (gemm1 out fp32)
__device__ float g_q32[C_DIM * NPIX];                 // 3 MB (dwconv Q out, fp32)
// LN output hi/lo fp16 [c][n]
__device__ unsigned short g_xh[C_DIM * NPIX];
__device__ unsigned short g_xl[C_DIM * NPIX];
// prepacked weights hi/lo fp16 [o][k]
__device__ unsigned short g_wqh[QKV_CH * C_DIM];
__device__ unsigned short g_wql[QKV_CH * C_DIM];
__device__ unsigned short g_wph[C_DIM * C_DIM];
__device__ unsigned short g_wpl[C_DIM * C_DIM];
// attention output hi/lo fp16 [c][n]
__device__ unsigned short g_ath[C_DIM * NPIX];
__device__ unsigned short g_atl[C_DIM * NPIX];
// prepacked K (hi/lo fp16, [head][key][32] cols 24..31 unused) and V fp16
__device__ unsigned short g_kh16[HEADS * NPIX * 32];
__device__ unsigned short g_kl16[HEADS * NPIX * 32];
__device__ unsigned short g_vh16[C_DIM * NPIX];

// ---------------- small helpers ----------------
__device__ __forceinline__ float ex2f_fast(float x) {
    float r;
    asm("ex2.approx.f32 %0, %1;" : "=f"(r) : "f"(x));
    return r;
}

__device__ __forceinline__ uint32_t h2ex2(uint32_t x) {
    uint32_t r;
    asm("ex2.approx.f16x2 %0, %1;" : "=r"(r) : "r"(x));
    return r;
}

__device__ __forceinline__ void mma16816(float c[4], const uint32_t a[4],
                                         uint32_t b0, uint32_t b1) {
    asm volatile(
        "mma.sync.aligned.m16n8k16.row.col.f32.f16.f16.f32 "
        "{%0,%1,%2,%3}, {%4,%5,%6,%7}, {%8,%9}, {%0,%1,%2,%3};"
        : "+f"(c[0]), "+f"(c[1]), "+f"(c[2]), "+f"(c[3])
        : "r"(a[0]), "r"(a[1]), "r"(a[2]), "r"(a[3]), "r"(b0), "r"(b1));
}

__device__ __forceinline__ void ldsm_x4(uint32_t& r0, uint32_t& r1,
                                        uint32_t& r2, uint32_t& r3, uint32_t addr) {
    asm volatile("ldmatrix.sync.aligned.m8n8.x4.shared.b16 {%0,%1,%2,%3}, [%4];"
                 : "=r"(r0), "=r"(r1), "=r"(r2), "=r"(r3) : "r"(addr));
}

__device__ __forceinline__ void ldsm_x4_t(uint32_t& r0, uint32_t& r1,
                                          uint32_t& r2, uint32_t& r3, uint32_t addr) {
    asm volatile("ldmatrix.sync.aligned.m8n8.x4.trans.shared.b16 {%0,%1,%2,%3}, [%4];"
                 : "=r"(r0), "=r"(r1), "=r"(r2), "=r"(r3) : "r"(addr));
}

__device__ __forceinline__ void cp16(uint32_t dst, const void* src) {
    asm volatile("cp.async.cg.shared.global [%0], [%1], 16;"
                 :: "r"(dst), "l"(src));
}

__device__ __forceinline__ uint32_t packh2(float x, float y) {
    __half2 h = __floats2half2_rn(x, y);
    return *(uint32_t*)&h;
}

// ---------------- Kernel 1: LayerNorm -> hi/lo fp16 [c][n] ----------------
__global__ void ln_kernel(const float* __restrict__ x,
                          const float* __restrict__ gamma,
                          const float* __restrict__ beta,
                          unsigned short* __restrict__ xh,
                          unsigned short* __restrict__ xl) {
    int p = blockIdx.x * blockDim.x + threadIdx.x;
    if (p >= NPIX) return;
    float s = 0.f, s2 = 0.f;
    #pragma unroll 8
    for (int c = 0; c < C_DIM; c++) {
        float v = x[c * NPIX + p];
        s += v;
        s2 = fmaf(v, v, s2);
    }
    const float invC = 1.0f / (float)C_DIM;
    float mean = s * invC;
    float var = s2 * invC - mean * mean;
    float inv = rsqrtf(var + 1e-5f);
    #pragma unroll 8
    for (int c = 0; c < C_DIM; c++) {
        float v = (x[c * NPIX + p] - mean) * inv;
        v = fmaf(v, gamma[c], beta[c]);
        __half h = __float2half_rn(v);
        xh[c * NPIX + p] = __half_as_ushort(h);
        xl[c * NPIX + p] = __half_as_ushort(__float2half_rn(v - __half2float(h)));
    }
}

// ---------------- Kernel 1b: weight prepack (hi/lo fp16 split) ----------------
__global__ void wprep_kernel(const float* __restrict__ wq, const float* __restrict__ wp,
                             unsigned short* __restrict__ wqh, unsigned short* __restrict__ wql,
                             unsigned short* __restrict__ wph, unsigned short* __restrict__ wpl) {
    int i = blockIdx.x * 256 + threadIdx.x;
    if (i < QKV_CH * C_DIM) {
        float v = wq[i];
        __half h = __float2half_rn(v);
        wqh[i] = __half_as_ushort(h);
        wql[i] = __half_as_ushort(__float2half_rn(v - __half2float(h)));
    }
    if (i < C_DIM * C_DIM) {
        float v = wp[i];
        __half h = __float2half_rn(v);
        wph[i] = __half_as_ushort(h);
        wpl[i] = __half_as_ushort(__float2half_rn(v - __half2float(h)));
    }
}

// ---------------- Kernel 2: tensor-core GEMM (hi/lo fp16 compensated) ----------
// Y[O,N] = W[O,K] @ B[K,N] (+ resid). W hi/lo [o][k]; B hi/lo [k][n].
// CTA: 64x64 tile, 128 threads (4 warps, each 16 o-rows x 64 n).
// 3-term compensation: WhBh + WhBl + WlBh (error ~2^-21).
__global__ __launch_bounds__(128) void gemm16_kernel(
        const unsigned short* __restrict__ Wh,
        const unsigned short* __restrict__ Wl,
        const unsigned short* __restrict__ Bh,
        const unsigned short* __restrict__ Bl,
        const float* __restrict__ resid,
        float* __restrict__ Y,
        int O, int K, int N) {
    __shared__ __align__(16) __half Wsh[64][40];
    __shared__ __align__(16) __half Wsl[64][40];
    __shared__ __align__(16) __half Xsh[32][72];
    __shared__ __align__(16) __half Xsl[32][72];
    const int tid = threadIdx.x;
    const int lane = tid & 31, warp = tid >> 5;
    const int g = lane >> 2, t = lane & 3;
    const int o0 = blockIdx.y * 64, n0 = blockIdx.x * 64;

    float acc[8][4];
    #pragma unroll
    for (int i = 0; i < 8; i++)
        #pragma unroll
        for (int j = 0; j < 4; j++) acc[i][j] = 0.f;

    const uint32_t xh_base = (uint32_t)__cvta_generic_to_shared(&Xsh[0][0])
                             + (uint32_t)(lane * 72) * 2;
    const uint32_t xl_base = (uint32_t)__cvta_generic_to_shared(&Xsl[0][0])
                             + (uint32_t)(lane * 72) * 2;

    for (int k0 = 0; k0 < K; k0 += 32) {
        if (k0) __syncthreads();
        {
            int row = tid >> 2, seg = tid & 3;
            #pragma unroll
            for (int rr = 0; rr < 2; rr++) {
                int r = row + rr * 32;
                *(uint4*)&Wsh[r][seg * 8] =
                    *(const uint4*)&Wh[(size_t)(o0 + r) * K + k0 + seg * 8];
                *(uint4*)&Wsl[r][seg * 8] =
                    *(const uint4*)&Wl[(size_t)(o0 + r) * K + k0 + seg * 8];
            }
            int xr = tid >> 3, xseg = tid & 7;
            #pragma unroll
            for (int rr = 0; rr < 2; rr++) {
                int k = xr + rr * 16;
                *(uint4*)&Xsh[k][xseg * 8] =
                    *(const uint4*)&Bh[(size_t)(k0 + k) * N + n0 + xseg * 8];
                *(uint4*)&Xsl[k][xseg * 8] =
                    *(const uint4*)&Bl[(size_t)(k0 + k) * N + n0 + xseg * 8];
            }
        }
        __syncthreads();

        uint32_t awh[2][4], awl[2][4];
        const int orr = warp * 16 + g;
        #pragma unroll
        for (int ks = 0; ks < 2; ks++) {
            int db = ks * 16 + t * 2;
            awh[ks][0] = *(const uint32_t*)&Wsh[orr][db];
            awh[ks][1] = *(const uint32_t*)&Wsh[orr + 8][db];
            awh[ks][2] = *(const uint32_t*)&Wsh[orr][db + 8];
            awh[ks][3] = *(const uint32_t*)&Wsh[orr + 8][db + 8];
            awl[ks][0] = *(const uint32_t*)&Wsl[orr][db];
            awl[ks][1] = *(const uint32_t*)&Wsl[orr + 8][db];
            awl[ks][2] = *(const uint32_t*)&Wsl[orr][db + 8];
            awl[ks][3] = *(const uint32_t*)&Wsl[orr + 8][db + 8];
        }
        #pragma unroll
        for (int nt = 0; nt < 8; nt++) {
            uint32_t bh0, bh1, bh2, bh3, bl0, bl1, bl2, bl3;
            ldsm_x4_t(bh0, bh1, bh2, bh3, xh_base + nt * 16);
            ldsm_x4_t(bl0, bl1, bl2, bl3, xl_base + nt * 16);
            mma16816(acc[nt], awh[0], bh0, bh1);
            mma16816(acc[nt], awh[1], bh2, bh3);
            mma16816(acc[nt], awh[0], bl0, bl1);
            mma16816(acc[nt], awh[1], bl2, bl3);
            mma16816(acc[nt], awl[0], bh0, bh1);
            mma16816(acc[nt], awl[1], bh2, bh3);
        }
    }

    const int orr = warp * 16 + g;
    #pragma unroll
    for (int nt = 0; nt < 8; nt++) {
        #pragma unroll
        for (int rr = 0; rr < 2; rr++) {
            int o = o0 + orr + rr * 8;
            int n = n0 + nt * 8 + t * 2;
            float v0 = acc[nt][rr * 2 + 0];
            float v1 = acc[nt][rr * 2 + 1];
            if (resid) {
                float2 rv = *(const float2*)&resid[(size_t)o * N + n];
                v0 += rv.x; v1 += rv.y;
            }
            float2 w2 = make_float2(v0, v1);
            *(float2*)&Y[(size_t)o * N + n] = w2;
        }
    }
}

// ---------------- Kernel 3: depthwise 3x3 conv + bias, fused K/V prepack ----
__global__ void dwconv_kernel(const float* __restrict__ in,
                              const float* __restrict__ w,
                              const float* __restrict__ b,
                              float* __restrict__ qout,
                              unsigned short* __restrict__ kh,
                              unsigned short* __restrict__ kl,
                              unsigned short* __restrict__ vh) {
    int idx = blockIdx.x * blockDim.x + threadIdx.x;
    if (idx >= QKV_CH * NPIX) return;
    int p = idx & (NPIX - 1);
    int xx = idx & (WW - 1);
    int yy = (idx >> 6) & (HH - 1);
    int ch = idx >> 12;
    const float* wp = &w[ch * 9];
    const float* base = &in[ch * NPIX];
    float acc = b[ch];
    #pragma unroll
    for (int dy = -1; dy <= 1; dy++) {
        int y2 = yy + dy;
        if (y2 < 0 || y2 >= HH) continue;
        #pragma unroll
        for (int dx = -1; dx <= 1; dx++) {
            int x2 = xx + dx;
            if (x2 < 0 || x2 >= WW) continue;
            acc = fmaf(base[y2 * WW + x2], wp[(dy + 1) * 3 + (dx + 1)], acc);
        }
    }
    if (ch < C_DIM) {
        qout[idx] = acc;
    } else if (ch < 2 * C_DIM) {
        int cc = ch - C_DIM;
        int hh2 = cc / HD;
        int dd = cc % HD;
        __half hi = __float2half_rn(acc);
        float lo = acc - __half2float(hi);
        size_t o = ((size_t)(hh2 * NPIX + p)) * 32 + dd;
        kh[o] = __half_as_ushort(hi);
        kl[o] = __half_as_ushort(__float2half_rn(lo));
    } else {
        vh[(size_t)(ch - 2 * C_DIM) * NPIX + p] =
            __half_as_ushort(__float2half_rn(acc));
    }
}

// ---------------- Kernel 4: tensor-core flash attention ----------------
// (round-12 structure; epilogue writes hi/lo fp16 [c][n])
#define ATT_Q  128
#define ATT_K  128
#define NCHUNK (NPIX / ATT_K)         // 32

#define OKB  0
#define KBUF 10240
#define OVB  (3 * KBUF)               // 30720
#define VBUF 4352                     // 32*136
#define SM_HALVES (OVB + 3 * VBUF)    // 43776
#define SMEM_BYTES (SM_HALVES * 2)    // 87552

__global__ __launch_bounds__(256, 2) void attn_mma_kernel(
        const float* __restrict__ q32,
        const unsigned short* __restrict__ kh,
        const unsigned short* __restrict__ kl,
        const unsigned short* __restrict__ vh,
        const float* __restrict__ temp,
        unsigned short* __restrict__ attH,
        unsigned short* __restrict__ attL) {
    extern __shared__ __align__(16) __half sm[];
    const int tid = threadIdx.x;
    const int lane = tid & 31;
    const int warp = tid >> 5;
    const int g = lane >> 2;
    const int t = lane & 3;

    const int h = blockIdx.y;
    const int q0 = blockIdx.x * ATT_Q;
    const float scale = temp[h] * 1.4426950408889634f;

    const float* qg = q32 + (h * HD) * NPIX;
    const unsigned short* khg = kh + (size_t)h * NPIX * 32;
    const unsigned short* klg = kl + (size_t)h * NPIX * 32;
    const unsigned short* vg  = vh + (size_t)(h * HD) * NPIX;

    const uint32_t smb = (uint32_t)__cvta_generic_to_shared(sm);

    // one-time init: K pad cols 24..31 (all bufs), V rows 24..31
    {
        uint32_t* smw = (uint32_t*)sm;
        for (int i = tid; i < 3072; i += 256) {
            int wds = i & 3;
            int r2 = i >> 2;
            int buf = r2 >> 8;
            int rem = r2 & 255;
            int part = rem >> 7;
            int row = rem & 127;
            int halfoff = OKB + buf * KBUF + part * 5120 + row * 40 + 24;
            smw[(halfoff >> 1) + wds] = 0;
        }
        for (int i = tid; i < 3 * 8 * 136; i += 256) {
            int buf = i / 1088;
            int rem = i - buf * 1088;
            int row = rem / 136;
            int col = rem - row * 136;
            sm[OVB + buf * VBUF + (24 + row) * 136 + col] =
                (row == 0) ? __float2half_rn(1.0f) : __ushort_as_half(0);
        }
    }

    auto issue_chunk = [&](int b, int m0) {
        uint32_t kdstH = smb + (OKB + b * KBUF) * 2;
        uint32_t kdstL = kdstH + 5120 * 2;
        uint32_t vdst  = smb + (OVB + b * VBUF) * 2;
        #pragma unroll
        for (int i = tid; i < 1152; i += 256) {
            if (i < 768) {
                int r = i;
                int part = r >= 384;
                r -= part * 384;
                int key = r / 3;
                int c = r - key * 3;
                const unsigned short* src =
                    (part ? klg : khg) + (size_t)(m0 + key) * 32 + c * 8;
                uint32_t dst = (part ? kdstL : kdstH) + (key * 40 + c * 8) * 2;
                cp16(dst, src);
            } else {
                int r = i - 768;
                int d = r >> 4;
                int c2 = r & 15;
                const unsigned short* src = vg + (size_t)d * NPIX + m0 + c2 * 8;
                uint32_t dst = vdst + (d * 136 + c2 * 8) * 2;
                cp16(dst, src);
            }
        }
        asm volatile("cp.async.commit_group;" ::: "memory");
    };
    issue_chunk(0, 0);
    issue_chunk(1, ATT_K);

    // Q A-fragments directly from global
    uint32_t aqh[2][4], aql[2][4];
    const int qr = warp * 16 + g;
    #pragma unroll
    for (int ks = 0; ks < 2; ks++) {
        #pragma unroll
        for (int r = 0; r < 4; r++) {
            int d0 = ks * 16 + t * 2 + ((r >= 2) ? 8 : 0);
            int qq = q0 + qr + (r & 1) * 8;
            if (d0 < HD) {
                float v0 = qg[d0 * NPIX + qq] * scale;
                float v1 = qg[(d0 + 1) * NPIX + qq] * scale;
                __half h0 = __float2half_rn(v0);
                __half h1 = __float2half_rn(v1);
                aqh[ks][r] = ((uint32_t)__half_as_ushort(h1) << 16) |
                             __half_as_ushort(h0);
                __half l0 = __float2half_rn(v0 - __half2float(h0));
                __half l1 = __float2half_rn(v1 - __half2float(h1));
                aql[ks][r] = ((uint32_t)__half_as_ushort(l1) << 16) |
                             __half_as_ushort(l0);
            } else {
                aqh[ks][r] = 0;
                aql[ks][r] = 0;
            }
        }
    }

    const int l7 = lane & 7;
    const int grp = lane >> 3;
    const uint32_t loff_k = (l7 * 40 + grp * 8) * 2;
    const uint32_t loff_v = (l7 * 136 + grp * 8) * 2;

    float out[4][4];
    #pragma unroll
    for (int i = 0; i < 4; i++)
        #pragma unroll
        for (int j = 0; j < 4; j++) out[i][j] = 0.f;
    float m_a = -1e30f, m_b = -1e30f;

    for (int ch = 0; ch < NCHUNK; ch++) {
        if (ch < NCHUNK - 1)
            asm volatile("cp.async.wait_group 1;" ::: "memory");
        else
            asm volatile("cp.async.wait_group 0;" ::: "memory");
        __syncthreads();
        if (ch + 2 < NCHUNK) issue_chunk((ch + 2) % 3, (ch + 2) * ATT_K);

        const int b = ch % 3;
        const uint32_t kbase = smb + (OKB + b * KBUF) * 2;
        const uint32_t vbase = smb + (OVB + b * VBUF) * 2;

        #pragma unroll
        for (int hc = 0; hc < 2; hc++) {
            const uint32_t kaddr_h = kbase + (uint32_t)hc * 5120 + loff_k;
            const uint32_t kaddr_l = kaddr_h + 5120 * 2;
            const uint32_t vaddr   = vbase + (uint32_t)hc * 128 + loff_v;

            float s[8][4];
            #pragma unroll
            for (int nt = 0; nt < 8; nt++) {
                uint32_t h0, h1, h2, h3, L0, L1, L2, L3;
                ldsm_x4(h0, h1, h2, h3, kaddr_h + nt * 640);
                ldsm_x4(L0, L1, L2, L3, kaddr_l + nt * 640);
                s[nt][0] = s[nt][1] = s[nt][2] = s[nt][3] = 0.f;
                mma16816(s[nt], aqh[0], h0, h1);
                mma16816(s[nt], aqh[1], h2, h3);
                mma16816(s[nt], aql[0], h0, h1);
                mma16816(s[nt], aql[1], h2, h3);
                mma16816(s[nt], aqh[0], L0, L1);
                mma16816(s[nt], aqh[1], L2, L3);
            }

            float ra = -1e30f, rb = -1e30f;
            #pragma unroll
            for (int nt = 0; nt < 8; nt++) {
                ra = fmaxf(ra, fmaxf(s[nt][0], s[nt][1]));
                rb = fmaxf(rb, fmaxf(s[nt][2], s[nt][3]));
            }
            ra = fmaxf(ra, __shfl_xor_sync(0xffffffffu, ra, 1));
            ra = fmaxf(ra, __shfl_xor_sync(0xffffffffu, ra, 2));
            rb = fmaxf(rb, __shfl_xor_sync(0xffffffffu, rb, 1));
            rb = fmaxf(rb, __shfl_xor_sync(0xffffffffu, rb, 2));
            float nma = fmaxf(m_a, ra);
            float nmb = fmaxf(m_b, rb);
            float ala = ex2f_fast(m_a - nma);
            float alb = ex2f_fast(m_b - nmb);
            m_a = nma; m_b = nmb;
            #pragma unroll
            for (int dnt = 0; dnt < 4; dnt++) {
                out[dnt][0] *= ala; out[dnt][1] *= ala;
                out[dnt][2] *= alb; out[dnt][3] *= alb;
            }

            uint32_t pa[4][4];
            #pragma unroll
            for (int kv = 0; kv < 4; kv++) {
                pa[kv][0] = h2ex2(packh2(s[2 * kv][0] - m_a,     s[2 * kv][1] - m_a));
                pa[kv][1] = h2ex2(packh2(s[2 * kv][2] - m_b,     s[2 * kv][3] - m_b));
                pa[kv][2] = h2ex2(packh2(s[2 * kv + 1][0] - m_a, s[2 * kv + 1][1] - m_a));
                pa[kv][3] = h2ex2(packh2(s[2 * kv + 1][2] - m_b, s[2 * kv + 1][3] - m_b));
            }

            #pragma unroll
            for (int dnt = 0; dnt < 4; dnt++) {
                uint32_t base = vaddr + (uint32_t)(dnt * 8) * 272;
                uint32_t v0, v1, v2, v3, v4, v5, v6, v7;
                ldsm_x4(v0, v1, v2, v3, base);
                ldsm_x4(v4, v5, v6, v7, base + 64);
                mma16816(out[dnt], pa[0], v0, v1);
                mma16816(out[dnt], pa[1], v2, v3);
                mma16816(out[dnt], pa[2], v4, v5);
                mma16816(out[dnt], pa[3], v6, v7);
            }
        }
    }

    // epilogue: normalize, split hi/lo, store [c][n]
    float l_a = __shfl_sync(0xffffffffu, out[3][0], lane & ~3);
    float l_b = __shfl_sync(0xffffffffu, out[3][2], lane & ~3);
    float inva = 1.0f / l_a;
    float invb = 1.0f / l_b;
    int qa = q0 + warp * 16 + g;
    int qb = qa + 8;
    #pragma unroll
    for (int dnt = 0; dnt < 3; dnt++) {
        int c0 = h * HD + dnt * 8 + t * 2;
        float v00 = out[dnt][0] * inva;
        float v01 = out[dnt][1] * inva;
        float v10 = out[dnt][2] * invb;
        float v11 = out[dnt][3] * invb;
        __half h00 = __float2half_rn(v00);
        __half h01 = __float2half_rn(v01);
        __half h10 = __float2half_rn(v10);
        __half h11 = __float2half_rn(v11);
        attH[c0 * NPIX + qa]       = __half_as_ushort(h00);
        attH[(c0 + 1) * NPIX + qa] = __half_as_ushort(h01);
        attH[c0 * NPIX + qb]       = __half_as_ushort(h10);
        attH[(c0 + 1) * NPIX + qb] = __half_as_ushort(h11);
        attL[c0 * NPIX + qa]       = __half_as_ushort(__float2half_rn(v00 - __half2float(h00)));
        attL[(c0 + 1) * NPIX + qa] = __half_as_ushort(__float2half_rn(v01 - __half2float(h01)));
        attL[c0 * NPIX + qb]       = __half_as_ushort(__float2half_rn(v10 - __half2float(h10)));
        attL[(c0 + 1) * NPIX + qb] = __half_as_ushort(__float2half_rn(v11 - __half2float(h11)));
    }
}

// ---------------- launch ----------------
extern "C" void kernel_launch(void* const* d_in, const int* in_sizes, int n_in,
                              void* d_out, int out_size) {
    const float* x      = (const float*)d_in[0];
    const float* gamma  = (const float*)d_in[1];
    const float* beta   = (const float*)d_in[2];
    const float* w_qkv  = (const float*)d_in[3];
    const float* w_dw   = (const float*)d_in[4];
    const float* b_dw   = (const float*)d_in[5];
    const float* w_proj = (const float*)d_in[6];
    const float* temper = (const float*)d_in[7];
    float* out = (float*)d_out;

    float *qkvb, *q32;
    unsigned short *xh, *xl, *wqh, *wql, *wph, *wpl, *ath, *atl, *kh, *kl, *vh;
    cudaGetSymbolAddress((void**)&qkvb, g_qkv);
    cudaGetSymbolAddress((void**)&q32,  g_q32);
    cudaGetSymbolAddress((void**)&xh,   g_xh);
    cudaGetSymbolAddress((void**)&xl,   g_xl);
    cudaGetSymbolAddress((void**)&wqh,  g_wqh);
    cudaGetSymbolAddress((void**)&wql,  g_wql);
    cudaGetSymbolAddress((void**)&wph,  g_wph);
    cudaGetSymbolAddress((void**)&wpl,  g_wpl);
    cudaGetSymbolAddress((void**)&ath,  g_ath);
    cudaGetSymbolAddress((void**)&atl,  g_atl);
    cudaGetSymbolAddress((void**)&kh,   g_kh16);
    cudaGetSymbolAddress((void**)&kl,   g_kl16);
    cudaGetSymbolAddress((void**)&vh,   g_vh16);

    cudaFuncSetAttribute(attn_mma_kernel,
                         cudaFuncAttributeMaxDynamicSharedMemorySize, SMEM_BYTES);

    // 0. weight prepack (independent)
    wprep_kernel<<<(QKV_CH * C_DIM + 255) / 256, 256>>>(w_qkv, w_proj,
                                                        wqh, wql, wph, wpl);

    // 1. LayerNorm -> hi/lo fp16
    ln_kernel<<<NPIX / 256, 256>>>(x, gamma, beta, xh, xl);

    // 2. qkv = w_qkv @ xln   [576,4096] fp32 out (tensor cores)
    {
        dim3 grid(NPIX / 64, QKV_CH / 64);
        gemm16_kernel<<<grid, 128>>>(wqh, wql, xh, xl, nullptr, qkvb,
                                     QKV_CH, C_DIM, NPIX);
    }

    // 3. depthwise 3x3 + bias, fused K/V fp16 prepack
    dwconv_kernel<<<(QKV_CH * NPIX) / 256, 256>>>(qkvb, w_dw, b_dw,
                                                  q32, kh, kl, vh);

    // 4. tensor-core flash attention -> att hi/lo fp16 [192,4096]
    {
        dim3 grid(NPIX / ATT_Q, HEADS);
        attn_mma_kernel<<<grid, 256, SMEM_BYTES>>>(q32, kh, kl, vh, temper,
                                                   ath, atl);
    }

    // 5. out = w_proj @ att + x  (tensor cores)
    {
        dim3 grid(NPIX / 64, C_DIM / 64);
        gemm16_kernel<<<grid, 128>>>(wph, wpl, ath, atl, x, out,
                                     C_DIM, C_DIM, NPIX);
    }
}